// round 7
// baseline (speedup 1.0000x reference)
#include <cuda_runtime.h>
#include <cuda_bf16.h>
#include <cstdint>

// ---------------------------------------------------------------------------
// Problem constants
// ---------------------------------------------------------------------------
#define B_WIN   2048
#define NTOK    49
#define DMODEL  768
#define NHEADS  24
#define HDIM    32
#define NW      64
#define MROWS   (B_WIN * NTOK)     // 100352
#define QKV_N   (3 * DMODEL)       // 2304
#define KDIM    768
#define KPITCH  (KDIM * 2)         // bytes per K-major row (bf16)

// ---------------------------------------------------------------------------
// scratch (__device__ globals, allocation-free)
// ---------------------------------------------------------------------------
__device__ float         g_qkv [(size_t)MROWS * QKV_N];
__device__ __nv_bfloat16 g_xhi [(size_t)MROWS * KDIM];
__device__ __nv_bfloat16 g_xlo [(size_t)MROWS * KDIM];
__device__ __nv_bfloat16 g_ahi [(size_t)MROWS * KDIM];
__device__ __nv_bfloat16 g_alo [(size_t)MROWS * KDIM];
__device__ __nv_bfloat16 g_w1hi[(size_t)QKV_N * KDIM];
__device__ __nv_bfloat16 g_w1lo[(size_t)QKV_N * KDIM];
__device__ __nv_bfloat16 g_w2hi[(size_t)DMODEL * KDIM];
__device__ __nv_bfloat16 g_w2lo[(size_t)DMODEL * KDIM];

// ---------------------------------------------------------------------------
// PTX helpers
// ---------------------------------------------------------------------------
__device__ __forceinline__ void cp16(uint32_t dst, const void* src) {
    asm volatile("cp.async.cg.shared.global [%0], [%1], 16;"
                 :: "r"(dst), "l"((unsigned long long)__cvta_generic_to_global(src))
                 : "memory");
}
__device__ __forceinline__ void ldsm4(uint32_t* r, uint32_t addr) {
    asm volatile("ldmatrix.sync.aligned.m8n8.x4.shared.b16 {%0,%1,%2,%3}, [%4];"
                 : "=r"(r[0]), "=r"(r[1]), "=r"(r[2]), "=r"(r[3]) : "r"(addr));
}
__device__ __forceinline__ void mma_bf16(float* c, const uint32_t* a,
                                         uint32_t b0, uint32_t b1) {
    asm volatile(
        "mma.sync.aligned.m16n8k16.row.col.f32.bf16.bf16.f32 "
        "{%0,%1,%2,%3}, {%4,%5,%6,%7}, {%8,%9}, {%0,%1,%2,%3};"
        : "+f"(c[0]), "+f"(c[1]), "+f"(c[2]), "+f"(c[3])
        : "r"(a[0]), "r"(a[1]), "r"(a[2]), "r"(a[3]), "r"(b0), "r"(b1));
}
// packed fp32x2 (Blackwell FFMA2 — PTX-only)
__device__ __forceinline__ unsigned long long dup_f32(float x) {
    unsigned long long r;
    asm("mov.b64 %0, {%1, %1};" : "=l"(r) : "f"(x));
    return r;
}
__device__ __forceinline__ unsigned long long pack_f32(float lo, float hi) {
    unsigned long long r;
    asm("mov.b64 %0, {%1, %2};" : "=l"(r) : "f"(lo), "f"(hi));
    return r;
}
__device__ __forceinline__ void fma2(unsigned long long& d,
                                     unsigned long long a,
                                     unsigned long long b) {
    asm("fma.rn.f32x2 %0, %1, %2, %0;" : "+l"(d) : "l"(a), "l"(b));
}
__device__ __forceinline__ void unpack2(unsigned long long v, float& lo, float& hi) {
    asm("mov.b64 {%0, %1}, %2;" : "=f"(lo), "=f"(hi) : "l"(v));
}

// ---------------------------------------------------------------------------
// GEMM: unchanged (77% tensor pipe, 2 CTAs/SM).
// ---------------------------------------------------------------------------
#define BM 128
#define BN 128
#define BK 32
#define NCHUNK (KDIM / BK)      // 24
#define AHI_OFF 0
#define ALO_OFF 8192
#define BHI_OFF 16384
#define BLO_OFF 24576
#define STG_B   32768
#define SMEM_TOTAL (3 * STG_B)  // 98304

extern __shared__ char dyn_smem[];

__device__ __forceinline__ uint32_t swz_off(int row, int c16) {
    return (uint32_t)(row * 64 + (((c16) ^ ((row >> 1) & 3)) << 4));
}

__global__ void __launch_bounds__(256, 2)
gemm_mma_kernel(const __nv_bfloat16* __restrict__ Ahi,
                const __nv_bfloat16* __restrict__ Alo,
                const __nv_bfloat16* __restrict__ Bhi,
                const __nv_bfloat16* __restrict__ Blo,
                const float* __restrict__ bias,
                float* __restrict__ C, int N)
{
    const uint32_t sb = (uint32_t)__cvta_generic_to_shared(dyn_smem);
    const int tid    = threadIdx.x;
    const int wid    = tid >> 5;
    const int lane   = tid & 31;
    const int warp_m = wid & 1;
    const int warp_n = wid >> 1;
    const int brow   = blockIdx.y * BM;
    const int bcol   = blockIdx.x * BN;

    const char* pAhi = (const char*)Ahi + (size_t)brow * KPITCH;
    const char* pAlo = (const char*)Alo + (size_t)brow * KPITCH;
    const char* pBhi = (const char*)Bhi + (size_t)bcol * KPITCH;
    const char* pBlo = (const char*)Blo + (size_t)bcol * KPITCH;

    float acc[4][4][4];
#pragma unroll
    for (int mt = 0; mt < 4; mt++)
#pragma unroll
        for (int nt = 0; nt < 4; nt++)
#pragma unroll
            for (int q = 0; q < 4; q++) acc[mt][nt][q] = 0.f;

    auto load_stage = [&](int c, int s) {
        const uint32_t st = sb + s * STG_B;
        const int koff = c * 64;
#pragma unroll
        for (int r = 0; r < 2; r++) {
            int p    = tid + r * 256;
            int row  = p >> 2;
            int c16  = p & 3;
            uint32_t so = swz_off(row, c16);
            size_t   go = (size_t)row * KPITCH + koff + c16 * 16;
            cp16(st + AHI_OFF + so, pAhi + go);
            cp16(st + ALO_OFF + so, pAlo + go);
            cp16(st + BHI_OFF + so, pBhi + go);
            cp16(st + BLO_OFF + so, pBlo + go);
        }
        asm volatile("cp.async.commit_group;" ::: "memory");
    };

    load_stage(0, 0);
    load_stage(1, 1);

    for (int c = 0; c < NCHUNK; c++) {
        if (c < NCHUNK - 1)
            asm volatile("cp.async.wait_group 1;" ::: "memory");
        else
            asm volatile("cp.async.wait_group 0;" ::: "memory");
        __syncthreads();

        if (c + 2 < NCHUNK) load_stage(c + 2, (c + 2) % 3);

        const uint32_t st = sb + (c % 3) * STG_B;
#pragma unroll
        for (int ks = 0; ks < 2; ks++) {
            uint32_t ahi[4][4], alo[4][4];
#pragma unroll
            for (int mt = 0; mt < 4; mt++) {
                int row = warp_m * 64 + mt * 16 + (lane & 7) + ((lane >> 3) & 1) * 8;
                int c16 = 2 * ks + ((lane >> 4) & 1);
                uint32_t so = swz_off(row, c16);
                ldsm4(ahi[mt], st + AHI_OFF + so);
                ldsm4(alo[mt], st + ALO_OFF + so);
            }
            uint32_t bh[2][4], bl[2][4];
#pragma unroll
            for (int np = 0; np < 2; np++) {
                int rowb = warp_n * 32 + np * 16 + (lane & 7) + ((lane >> 4) & 1) * 8;
                int c16  = 2 * ks + ((lane >> 3) & 1);
                uint32_t so = swz_off(rowb, c16);
                ldsm4(bh[np], st + BHI_OFF + so);
                ldsm4(bl[np], st + BLO_OFF + so);
            }
#pragma unroll
            for (int np = 0; np < 2; np++)
#pragma unroll
                for (int t = 0; t < 2; t++)
#pragma unroll
                    for (int mt = 0; mt < 4; mt++)
                        mma_bf16(acc[mt][np*2+t], ahi[mt], bh[np][t*2], bh[np][t*2+1]);
#pragma unroll
            for (int np = 0; np < 2; np++)
#pragma unroll
                for (int t = 0; t < 2; t++)
#pragma unroll
                    for (int mt = 0; mt < 4; mt++)
                        mma_bf16(acc[mt][np*2+t], ahi[mt], bl[np][t*2], bl[np][t*2+1]);
#pragma unroll
            for (int np = 0; np < 2; np++)
#pragma unroll
                for (int t = 0; t < 2; t++)
#pragma unroll
                    for (int mt = 0; mt < 4; mt++)
                        mma_bf16(acc[mt][np*2+t], alo[mt], bh[np][t*2], bh[np][t*2+1]);
        }
    }

    const int row0 = brow + warp_m * 64;
    const int col0 = bcol + warp_n * 32;
#pragma unroll
    for (int mt = 0; mt < 4; mt++) {
#pragma unroll
        for (int nt = 0; nt < 4; nt++) {
            int r  = row0 + mt * 16 + (lane >> 2);
            int cc = col0 + nt * 8 + (lane & 3) * 2;
            float2 bv = *(const float2*)(bias + cc);
            float2 o0 = make_float2(acc[mt][nt][0] + bv.x, acc[mt][nt][1] + bv.y);
            float2 o1 = make_float2(acc[mt][nt][2] + bv.x, acc[mt][nt][3] + bv.y);
            *(float2*)(C + (size_t)r * N + cc)       = o0;
            *(float2*)(C + (size_t)(r + 8) * N + cc) = o1;
        }
    }
}

// ---------------------------------------------------------------------------
// split f32 -> (hi, lo) bf16
// ---------------------------------------------------------------------------
__global__ void __launch_bounds__(256)
split_kernel(const float4* __restrict__ in, uint2* __restrict__ hi,
             uint2* __restrict__ lo, int n4)
{
    int i = blockIdx.x * 256 + threadIdx.x;
    if (i >= n4) return;
    float4 v = in[i];
    __nv_bfloat16 h0 = __float2bfloat16(v.x);
    __nv_bfloat16 h1 = __float2bfloat16(v.y);
    __nv_bfloat16 h2 = __float2bfloat16(v.z);
    __nv_bfloat16 h3 = __float2bfloat16(v.w);
    __nv_bfloat16 l0 = __float2bfloat16(v.x - __bfloat162float(h0));
    __nv_bfloat16 l1 = __float2bfloat16(v.y - __bfloat162float(h1));
    __nv_bfloat16 l2 = __float2bfloat16(v.z - __bfloat162float(h2));
    __nv_bfloat16 l3 = __float2bfloat16(v.w - __bfloat162float(h3));
    __nv_bfloat162 hh0 = {h0, h1}, hh1 = {h2, h3};
    __nv_bfloat162 ll0 = {l0, l1}, ll1 = {l2, l3};
    uint2 ho, lw;
    ho.x = *(uint32_t*)&hh0; ho.y = *(uint32_t*)&hh1;
    lw.x = *(uint32_t*)&ll0; lw.y = *(uint32_t*)&ll1;
    hi[i] = ho; lo[i] = lw;
}

// ---------------------------------------------------------------------------
// weight transpose + split: W[K,N] f32 -> hi/lo[N,K] bf16
// ---------------------------------------------------------------------------
__global__ void __launch_bounds__(256)
wtrans_split_kernel(const float* __restrict__ W, __nv_bfloat16* __restrict__ hi,
                    __nv_bfloat16* __restrict__ lo, int K, int N)
{
    __shared__ float t[32][33];
    const int n0 = blockIdx.x * 32, k0 = blockIdx.y * 32;
    const int tx = threadIdx.x & 31, ty = threadIdx.x >> 5;
#pragma unroll
    for (int r = 0; r < 32; r += 8)
        t[ty + r][tx] = W[(size_t)(k0 + ty + r) * N + n0 + tx];
    __syncthreads();
#pragma unroll
    for (int r = 0; r < 32; r += 8) {
        float v = t[tx][ty + r];
        size_t o = (size_t)(n0 + ty + r) * K + k0 + tx;
        __nv_bfloat16 h = __float2bfloat16(v);
        hi[o] = h;
        lo[o] = __float2bfloat16(v - __bfloat162float(h));
    }
}

// ---------------------------------------------------------------------------
// Attention: one CTA per (window, head), 256 threads / 8 warps.
// K held in smem as packed f32x2 pairs kp2[d][j] = {k[j][d], k[j+32][d]}
// -> low register pressure -> ~5 CTAs/SM (10 warps/SMSP) to hide latency.
// No max-subtraction (logits bounded). Warp w owns rows i = w, w+8, ...
// ---------------------------------------------------------------------------
#define VT_STRIDE 52
#define ATT_THREADS 256

__global__ void __launch_bounds__(ATT_THREADS)
attn_kernel(const float* __restrict__ qkv,
            const float* __restrict__ mask,
            const float* __restrict__ bias_table,
            __nv_bfloat16* __restrict__ out_hi,
            __nv_bfloat16* __restrict__ out_lo)
{
    const int bh = blockIdx.x;
    const int b  = bh / NHEADS;
    const int h  = bh - b * NHEADS;
    const int w  = b & (NW - 1);

    __shared__ float qs[NTOK * HDIM];                    // q[i][d]
    __shared__ unsigned long long kp2[HDIM * 32];        // {k[j][d],k[j+32][d]}
    __shared__ float vt[HDIM * VT_STRIDE];               // v^T[d][j]
    __shared__ float pbuf[8][64];
    __shared__ float bt[169];

    const int tid  = threadIdx.x;
    const int warp = tid >> 5, lane = tid & 31;
    const float* base = qkv + (size_t)b * NTOK * QKV_N + h * HDIM;

    // ---- q fill (float4, coalesced) ----
    for (int idx = tid; idx < NTOK * 8; idx += ATT_THREADS) {
        int i = idx >> 3, m = idx & 7;
        *(float4*)&qs[i * HDIM + m * 4] =
            *(const float4*)(base + (size_t)i * QKV_N + m * 4);
    }
    // ---- K fill: warp w covers dims d0 = w*4 .. w*4+3; lane = j ----
    {
        const int d0 = warp * 4;
        const int j  = lane;
        float4 kv1 = *(const float4*)(base + (size_t)j * QKV_N + DMODEL + d0);
        float4 kv2 = make_float4(0.f, 0.f, 0.f, 0.f);
        if (j < NTOK - 32)
            kv2 = *(const float4*)(base + (size_t)(j + 32) * QKV_N + DMODEL + d0);
        kp2[(d0 + 0) * 32 + j] = pack_f32(kv1.x, kv2.x);
        kp2[(d0 + 1) * 32 + j] = pack_f32(kv1.y, kv2.y);
        kp2[(d0 + 2) * 32 + j] = pack_f32(kv1.z, kv2.z);
        kp2[(d0 + 3) * 32 + j] = pack_f32(kv1.w, kv2.w);
    }
    // ---- V^T fill ----
    if (tid < NTOK) {
        const float* vrow = base + (size_t)tid * QKV_N + 2 * DMODEL;
#pragma unroll
        for (int m = 0; m < 8; m++) {
            float4 vv = *(const float4*)(vrow + 4 * m);
            vt[(4 * m + 0) * VT_STRIDE + tid] = vv.x;
            vt[(4 * m + 1) * VT_STRIDE + tid] = vv.y;
            vt[(4 * m + 2) * VT_STRIDE + tid] = vv.z;
            vt[(4 * m + 3) * VT_STRIDE + tid] = vv.w;
        }
    }
    if (tid >= 64 && tid < 96) {
        int d = tid - 64;
        vt[d * VT_STRIDE + 49] = 0.f;
        vt[d * VT_STRIDE + 50] = 0.f;
        vt[d * VT_STRIDE + 51] = 0.f;
    }
    for (int idx = tid; idx < 169; idx += ATT_THREADS)
        bt[idx] = bias_table[idx * NHEADS + h];
    __syncthreads();

    const float scale = 0.17677669529663687f;
    const float* mrow_base = mask + (size_t)w * NTOK * NTOK;

    const int yq  = lane / 7, xq  = lane - yq * 7;
    const int j2  = lane + 32;
    const int yq2 = j2 / 7,   xq2 = j2 - yq2 * 7;

    for (int i = warp; i < NTOK; i += 8) {
        const int yi = i / 7, xi = i - yi * 7;
        const float* mrow = mrow_base + (size_t)i * NTOK;

        unsigned long long d12 = 0ull;
#pragma unroll
        for (int m = 0; m < 8; m++) {
            float4 qv = *(const float4*)&qs[i * HDIM + 4 * m];   // broadcast
            fma2(d12, kp2[(4*m+0) * 32 + lane], dup_f32(qv.x));
            fma2(d12, kp2[(4*m+1) * 32 + lane], dup_f32(qv.y));
            fma2(d12, kp2[(4*m+2) * 32 + lane], dup_f32(qv.z));
            fma2(d12, kp2[(4*m+3) * 32 + lane], dup_f32(qv.w));
        }
        float d1, d2;
        unpack2(d12, d1, d2);

        float l1 = d1 * scale + bt[(yi - yq + 6) * 13 + (xi - xq + 6)] + mrow[lane];
        float p1 = __expf(l1);
        float p2 = 0.f;
        if (lane < NTOK - 32) {
            float l2 = d2 * scale + bt[(yi - yq2 + 6) * 13 + (xi - xq2 + 6)] + mrow[j2];
            p2 = __expf(l2);
        }
        float s = p1 + p2;
#pragma unroll
        for (int o = 16; o > 0; o >>= 1)
            s += __shfl_xor_sync(0xffffffffu, s, o);
        float inv = 1.f / s;

        pbuf[warp][lane]      = p1 * inv;
        pbuf[warp][lane + 32] = p2 * inv;   // zero for lane>=17 (covers 49..63)
        __syncwarp();

        unsigned long long a2 = 0ull;
#pragma unroll
        for (int j4 = 0; j4 < 13; j4++) {
            ulonglong2 pq = *(const ulonglong2*)&pbuf[warp][j4 * 4];      // bcast
            ulonglong2 vq = *(const ulonglong2*)&vt[lane * VT_STRIDE + j4 * 4];
            fma2(a2, pq.x, vq.x);
            fma2(a2, pq.y, vq.y);
        }
        float alo_, ahi_;
        unpack2(a2, alo_, ahi_);
        float acc = alo_ + ahi_;

        size_t oidx = ((size_t)b * NTOK + i) * DMODEL + h * HDIM + lane;
        __nv_bfloat16 hh = __float2bfloat16(acc);
        out_hi[oidx] = hh;
        out_lo[oidx] = __float2bfloat16(acc - __bfloat162float(hh));
        __syncwarp();
    }
}

// ---------------------------------------------------------------------------
// launch
// ---------------------------------------------------------------------------
extern "C" void kernel_launch(void* const* d_in, const int* in_sizes, int n_in,
                              void* d_out, int out_size)
{
    const float* x          = (const float*)d_in[0];
    const float* mask       = (const float*)d_in[1];
    const float* qkv_w      = (const float*)d_in[2];
    const float* qkv_b      = (const float*)d_in[3];
    const float* proj_w     = (const float*)d_in[4];
    const float* proj_b     = (const float*)d_in[5];
    const float* bias_table = (const float*)d_in[6];
    float* out = (float*)d_out;

    float *qkv_s;
    __nv_bfloat16 *xhi, *xlo, *ahi, *alo, *w1hi, *w1lo, *w2hi, *w2lo;
    cudaGetSymbolAddress((void**)&qkv_s, g_qkv);
    cudaGetSymbolAddress((void**)&xhi,  g_xhi);
    cudaGetSymbolAddress((void**)&xlo,  g_xlo);
    cudaGetSymbolAddress((void**)&ahi,  g_ahi);
    cudaGetSymbolAddress((void**)&alo,  g_alo);
    cudaGetSymbolAddress((void**)&w1hi, g_w1hi);
    cudaGetSymbolAddress((void**)&w1lo, g_w1lo);
    cudaGetSymbolAddress((void**)&w2hi, g_w2hi);
    cudaGetSymbolAddress((void**)&w2lo, g_w2lo);

    cudaFuncSetAttribute(gemm_mma_kernel,
                         cudaFuncAttributeMaxDynamicSharedMemorySize, SMEM_TOTAL);

    {
        int n4 = (MROWS * KDIM) / 4;
        split_kernel<<<(n4 + 255) / 256, 256>>>((const float4*)x,
                                                (uint2*)xhi, (uint2*)xlo, n4);
        dim3 g1(QKV_N / 32, KDIM / 32);
        wtrans_split_kernel<<<g1, 256>>>(qkv_w, w1hi, w1lo, KDIM, QKV_N);
        dim3 g2(DMODEL / 32, KDIM / 32);
        wtrans_split_kernel<<<g2, 256>>>(proj_w, w2hi, w2lo, KDIM, DMODEL);
    }
    {
        dim3 grid(QKV_N / BN, MROWS / BM);
        gemm_mma_kernel<<<grid, 256, SMEM_TOTAL>>>(xhi, xlo, w1hi, w1lo,
                                                   qkv_b, qkv_s, QKV_N);
    }
    attn_kernel<<<B_WIN * NHEADS, ATT_THREADS>>>(qkv_s, mask, bias_table, ahi, alo);
    {
        dim3 grid(DMODEL / BN, MROWS / BM);
        gemm_mma_kernel<<<grid, 256, SMEM_TOTAL>>>(ahi, alo, w2hi, w2lo,
                                                   proj_b, out, DMODEL);
    }
}

// round 8
// speedup vs baseline: 1.1572x; 1.1572x over previous
#include <cuda_runtime.h>
#include <cuda_bf16.h>
#include <cstdint>

// ---------------------------------------------------------------------------
// Problem constants
// ---------------------------------------------------------------------------
#define B_WIN   2048
#define NTOK    49
#define DMODEL  768
#define NHEADS  24
#define HDIM    32
#define NW      64
#define MROWS   (B_WIN * NTOK)     // 100352
#define QKV_N   (3 * DMODEL)       // 2304
#define KDIM    768
#define KPITCH  (KDIM * 2)         // bytes per K-major row (bf16)

// ---------------------------------------------------------------------------
// scratch (__device__ globals, allocation-free)
// ---------------------------------------------------------------------------
__device__ float         g_qkv [(size_t)MROWS * QKV_N];
__device__ __nv_bfloat16 g_xhi [(size_t)MROWS * KDIM];
__device__ __nv_bfloat16 g_xlo [(size_t)MROWS * KDIM];
__device__ __nv_bfloat16 g_ahi [(size_t)MROWS * KDIM];
__device__ __nv_bfloat16 g_alo [(size_t)MROWS * KDIM];
__device__ __nv_bfloat16 g_w1hi[(size_t)QKV_N * KDIM];
__device__ __nv_bfloat16 g_w1lo[(size_t)QKV_N * KDIM];
__device__ __nv_bfloat16 g_w2hi[(size_t)DMODEL * KDIM];
__device__ __nv_bfloat16 g_w2lo[(size_t)DMODEL * KDIM];

// ---------------------------------------------------------------------------
// PTX helpers
// ---------------------------------------------------------------------------
__device__ __forceinline__ void cp16(uint32_t dst, const void* src) {
    asm volatile("cp.async.cg.shared.global [%0], [%1], 16;"
                 :: "r"(dst), "l"((unsigned long long)__cvta_generic_to_global(src))
                 : "memory");
}
__device__ __forceinline__ void ldsm4(uint32_t* r, uint32_t addr) {
    asm volatile("ldmatrix.sync.aligned.m8n8.x4.shared.b16 {%0,%1,%2,%3}, [%4];"
                 : "=r"(r[0]), "=r"(r[1]), "=r"(r[2]), "=r"(r[3]) : "r"(addr));
}
__device__ __forceinline__ void mma_bf16(float* c, const uint32_t* a,
                                         uint32_t b0, uint32_t b1) {
    asm volatile(
        "mma.sync.aligned.m16n8k16.row.col.f32.bf16.bf16.f32 "
        "{%0,%1,%2,%3}, {%4,%5,%6,%7}, {%8,%9}, {%0,%1,%2,%3};"
        : "+f"(c[0]), "+f"(c[1]), "+f"(c[2]), "+f"(c[3])
        : "r"(a[0]), "r"(a[1]), "r"(a[2]), "r"(a[3]), "r"(b0), "r"(b1));
}
// packed fp32x2 (Blackwell FFMA2 — PTX-only)
__device__ __forceinline__ unsigned long long dup_f32(float x) {
    unsigned long long r;
    asm("mov.b64 %0, {%1, %1};" : "=l"(r) : "f"(x));
    return r;
}
__device__ __forceinline__ unsigned long long pack_f32(float lo, float hi) {
    unsigned long long r;
    asm("mov.b64 %0, {%1, %2};" : "=l"(r) : "f"(lo), "f"(hi));
    return r;
}
__device__ __forceinline__ void fma2(unsigned long long& d,
                                     unsigned long long a,
                                     unsigned long long b) {
    asm("fma.rn.f32x2 %0, %1, %2, %0;" : "+l"(d) : "l"(a), "l"(b));
}
__device__ __forceinline__ void unpack2(unsigned long long v, float& lo, float& hi) {
    asm("mov.b64 {%0, %1}, %2;" : "=f"(lo), "=f"(hi) : "l"(v));
}

// ---------------------------------------------------------------------------
// GEMM: unchanged (77% tensor pipe, 2 CTAs/SM).
// ---------------------------------------------------------------------------
#define BM 128
#define BN 128
#define BK 32
#define NCHUNK (KDIM / BK)      // 24
#define AHI_OFF 0
#define ALO_OFF 8192
#define BHI_OFF 16384
#define BLO_OFF 24576
#define STG_B   32768
#define SMEM_TOTAL (3 * STG_B)  // 98304

extern __shared__ char dyn_smem[];

__device__ __forceinline__ uint32_t swz_off(int row, int c16) {
    return (uint32_t)(row * 64 + (((c16) ^ ((row >> 1) & 3)) << 4));
}

__global__ void __launch_bounds__(256, 2)
gemm_mma_kernel(const __nv_bfloat16* __restrict__ Ahi,
                const __nv_bfloat16* __restrict__ Alo,
                const __nv_bfloat16* __restrict__ Bhi,
                const __nv_bfloat16* __restrict__ Blo,
                const float* __restrict__ bias,
                float* __restrict__ C, int N)
{
    const uint32_t sb = (uint32_t)__cvta_generic_to_shared(dyn_smem);
    const int tid    = threadIdx.x;
    const int wid    = tid >> 5;
    const int lane   = tid & 31;
    const int warp_m = wid & 1;
    const int warp_n = wid >> 1;
    const int brow   = blockIdx.y * BM;
    const int bcol   = blockIdx.x * BN;

    const char* pAhi = (const char*)Ahi + (size_t)brow * KPITCH;
    const char* pAlo = (const char*)Alo + (size_t)brow * KPITCH;
    const char* pBhi = (const char*)Bhi + (size_t)bcol * KPITCH;
    const char* pBlo = (const char*)Blo + (size_t)bcol * KPITCH;

    float acc[4][4][4];
#pragma unroll
    for (int mt = 0; mt < 4; mt++)
#pragma unroll
        for (int nt = 0; nt < 4; nt++)
#pragma unroll
            for (int q = 0; q < 4; q++) acc[mt][nt][q] = 0.f;

    auto load_stage = [&](int c, int s) {
        const uint32_t st = sb + s * STG_B;
        const int koff = c * 64;
#pragma unroll
        for (int r = 0; r < 2; r++) {
            int p    = tid + r * 256;
            int row  = p >> 2;
            int c16  = p & 3;
            uint32_t so = swz_off(row, c16);
            size_t   go = (size_t)row * KPITCH + koff + c16 * 16;
            cp16(st + AHI_OFF + so, pAhi + go);
            cp16(st + ALO_OFF + so, pAlo + go);
            cp16(st + BHI_OFF + so, pBhi + go);
            cp16(st + BLO_OFF + so, pBlo + go);
        }
        asm volatile("cp.async.commit_group;" ::: "memory");
    };

    load_stage(0, 0);
    load_stage(1, 1);

    for (int c = 0; c < NCHUNK; c++) {
        if (c < NCHUNK - 1)
            asm volatile("cp.async.wait_group 1;" ::: "memory");
        else
            asm volatile("cp.async.wait_group 0;" ::: "memory");
        __syncthreads();

        if (c + 2 < NCHUNK) load_stage(c + 2, (c + 2) % 3);

        const uint32_t st = sb + (c % 3) * STG_B;
#pragma unroll
        for (int ks = 0; ks < 2; ks++) {
            uint32_t ahi[4][4], alo[4][4];
#pragma unroll
            for (int mt = 0; mt < 4; mt++) {
                int row = warp_m * 64 + mt * 16 + (lane & 7) + ((lane >> 3) & 1) * 8;
                int c16 = 2 * ks + ((lane >> 4) & 1);
                uint32_t so = swz_off(row, c16);
                ldsm4(ahi[mt], st + AHI_OFF + so);
                ldsm4(alo[mt], st + ALO_OFF + so);
            }
            uint32_t bh[2][4], bl[2][4];
#pragma unroll
            for (int np = 0; np < 2; np++) {
                int rowb = warp_n * 32 + np * 16 + (lane & 7) + ((lane >> 4) & 1) * 8;
                int c16  = 2 * ks + ((lane >> 3) & 1);
                uint32_t so = swz_off(rowb, c16);
                ldsm4(bh[np], st + BHI_OFF + so);
                ldsm4(bl[np], st + BLO_OFF + so);
            }
#pragma unroll
            for (int np = 0; np < 2; np++)
#pragma unroll
                for (int t = 0; t < 2; t++)
#pragma unroll
                    for (int mt = 0; mt < 4; mt++)
                        mma_bf16(acc[mt][np*2+t], ahi[mt], bh[np][t*2], bh[np][t*2+1]);
#pragma unroll
            for (int np = 0; np < 2; np++)
#pragma unroll
                for (int t = 0; t < 2; t++)
#pragma unroll
                    for (int mt = 0; mt < 4; mt++)
                        mma_bf16(acc[mt][np*2+t], ahi[mt], bl[np][t*2], bl[np][t*2+1]);
#pragma unroll
            for (int np = 0; np < 2; np++)
#pragma unroll
                for (int t = 0; t < 2; t++)
#pragma unroll
                    for (int mt = 0; mt < 4; mt++)
                        mma_bf16(acc[mt][np*2+t], alo[mt], bh[np][t*2], bh[np][t*2+1]);
        }
    }

    const int row0 = brow + warp_m * 64;
    const int col0 = bcol + warp_n * 32;
#pragma unroll
    for (int mt = 0; mt < 4; mt++) {
#pragma unroll
        for (int nt = 0; nt < 4; nt++) {
            int r  = row0 + mt * 16 + (lane >> 2);
            int cc = col0 + nt * 8 + (lane & 3) * 2;
            float2 bv = *(const float2*)(bias + cc);
            float2 o0 = make_float2(acc[mt][nt][0] + bv.x, acc[mt][nt][1] + bv.y);
            float2 o1 = make_float2(acc[mt][nt][2] + bv.x, acc[mt][nt][3] + bv.y);
            *(float2*)(C + (size_t)r * N + cc)       = o0;
            *(float2*)(C + (size_t)(r + 8) * N + cc) = o1;
        }
    }
}

// ---------------------------------------------------------------------------
// split f32 -> (hi, lo) bf16
// ---------------------------------------------------------------------------
__global__ void __launch_bounds__(256)
split_kernel(const float4* __restrict__ in, uint2* __restrict__ hi,
             uint2* __restrict__ lo, int n4)
{
    int i = blockIdx.x * 256 + threadIdx.x;
    if (i >= n4) return;
    float4 v = in[i];
    __nv_bfloat16 h0 = __float2bfloat16(v.x);
    __nv_bfloat16 h1 = __float2bfloat16(v.y);
    __nv_bfloat16 h2 = __float2bfloat16(v.z);
    __nv_bfloat16 h3 = __float2bfloat16(v.w);
    __nv_bfloat16 l0 = __float2bfloat16(v.x - __bfloat162float(h0));
    __nv_bfloat16 l1 = __float2bfloat16(v.y - __bfloat162float(h1));
    __nv_bfloat16 l2 = __float2bfloat16(v.z - __bfloat162float(h2));
    __nv_bfloat16 l3 = __float2bfloat16(v.w - __bfloat162float(h3));
    __nv_bfloat162 hh0 = {h0, h1}, hh1 = {h2, h3};
    __nv_bfloat162 ll0 = {l0, l1}, ll1 = {l2, l3};
    uint2 ho, lw;
    ho.x = *(uint32_t*)&hh0; ho.y = *(uint32_t*)&hh1;
    lw.x = *(uint32_t*)&ll0; lw.y = *(uint32_t*)&ll1;
    hi[i] = ho; lo[i] = lw;
}

// ---------------------------------------------------------------------------
// weight transpose + split: W[K,N] f32 -> hi/lo[N,K] bf16
// ---------------------------------------------------------------------------
__global__ void __launch_bounds__(256)
wtrans_split_kernel(const float* __restrict__ W, __nv_bfloat16* __restrict__ hi,
                    __nv_bfloat16* __restrict__ lo, int K, int N)
{
    __shared__ float t[32][33];
    const int n0 = blockIdx.x * 32, k0 = blockIdx.y * 32;
    const int tx = threadIdx.x & 31, ty = threadIdx.x >> 5;
#pragma unroll
    for (int r = 0; r < 32; r += 8)
        t[ty + r][tx] = W[(size_t)(k0 + ty + r) * N + n0 + tx];
    __syncthreads();
#pragma unroll
    for (int r = 0; r < 32; r += 8) {
        float v = t[tx][ty + r];
        size_t o = (size_t)(n0 + ty + r) * K + k0 + tx;
        __nv_bfloat16 h = __float2bfloat16(v);
        hi[o] = h;
        lo[o] = __float2bfloat16(v - __bfloat162float(h));
    }
}

// ---------------------------------------------------------------------------
// Attention: one CTA per (window, head), 128 threads / 4 warps.
// ROW-BATCHED: each warp processes its 13 rows SIMULTANEOUSLY — K/V smem
// reads are amortized 13x and softmax/qk/pv chains get 13-way ILP.
// Warp w owns rows [13w, 13w+nr), nr = 13,13,13,10.
// ---------------------------------------------------------------------------
#define VT_STRIDE 52
#define RPW 13            // max rows per warp

__global__ void __launch_bounds__(128)
attn_kernel(const float* __restrict__ qkv,
            const float* __restrict__ mask,
            const float* __restrict__ bias_table,
            __nv_bfloat16* __restrict__ out_hi,
            __nv_bfloat16* __restrict__ out_lo)
{
    const int bh = blockIdx.x;
    const int b  = bh / NHEADS;
    const int h  = bh - b * NHEADS;
    const int w  = b & (NW - 1);

    __shared__ float qs[NTOK * HDIM];                 // q[i][d]
    __shared__ unsigned long long kp2[HDIM * 32];     // {k[j][d],k[j+32][d]}
    __shared__ float vt[HDIM * VT_STRIDE];            // v^T[d][j] (+zero pad)
    __shared__ float pbuf[4][RPW][64];                // probs per warp per row
    __shared__ float bt[169];

    const int tid  = threadIdx.x;
    const int warp = tid >> 5, lane = tid & 31;
    const float* base = qkv + (size_t)b * NTOK * QKV_N + h * HDIM;

    // ---- q fill (float4, coalesced) ----
    for (int idx = tid; idx < NTOK * 8; idx += 128) {
        int i = idx >> 3, m = idx & 7;
        *(float4*)&qs[i * HDIM + m * 4] =
            *(const float4*)(base + (size_t)i * QKV_N + m * 4);
    }
    // ---- K fill: warp covers dims d0 = 8w..8w+7, lane = j ----
    {
        const int d0 = warp * 8;
        const int j  = lane;
        float4 a1 = *(const float4*)(base + (size_t)j * QKV_N + DMODEL + d0);
        float4 b1 = *(const float4*)(base + (size_t)j * QKV_N + DMODEL + d0 + 4);
        float4 a2 = make_float4(0.f, 0.f, 0.f, 0.f);
        float4 b2 = make_float4(0.f, 0.f, 0.f, 0.f);
        if (j < NTOK - 32) {
            a2 = *(const float4*)(base + (size_t)(j + 32) * QKV_N + DMODEL + d0);
            b2 = *(const float4*)(base + (size_t)(j + 32) * QKV_N + DMODEL + d0 + 4);
        }
        kp2[(d0 + 0) * 32 + j] = pack_f32(a1.x, a2.x);
        kp2[(d0 + 1) * 32 + j] = pack_f32(a1.y, a2.y);
        kp2[(d0 + 2) * 32 + j] = pack_f32(a1.z, a2.z);
        kp2[(d0 + 3) * 32 + j] = pack_f32(a1.w, a2.w);
        kp2[(d0 + 4) * 32 + j] = pack_f32(b1.x, b2.x);
        kp2[(d0 + 5) * 32 + j] = pack_f32(b1.y, b2.y);
        kp2[(d0 + 6) * 32 + j] = pack_f32(b1.z, b2.z);
        kp2[(d0 + 7) * 32 + j] = pack_f32(b1.w, b2.w);
    }
    // ---- V^T fill ----
    if (tid < NTOK) {
        const float* vrow = base + (size_t)tid * QKV_N + 2 * DMODEL;
#pragma unroll
        for (int m = 0; m < 8; m++) {
            float4 vv = *(const float4*)(vrow + 4 * m);
            vt[(4 * m + 0) * VT_STRIDE + tid] = vv.x;
            vt[(4 * m + 1) * VT_STRIDE + tid] = vv.y;
            vt[(4 * m + 2) * VT_STRIDE + tid] = vv.z;
            vt[(4 * m + 3) * VT_STRIDE + tid] = vv.w;
        }
    }
    if (tid >= 64 && tid < 96) {
        int d = tid - 64;
        vt[d * VT_STRIDE + 49] = 0.f;
        vt[d * VT_STRIDE + 50] = 0.f;
        vt[d * VT_STRIDE + 51] = 0.f;
    }
    for (int idx = tid; idx < 169; idx += 128)
        bt[idx] = bias_table[idx * NHEADS + h];
    __syncthreads();

    const float scale = 0.17677669529663687f;
    const float* mrow_base = mask + (size_t)w * NTOK * NTOK;

    const int row0 = warp * RPW;
    const int nr   = (NTOK - row0 < RPW) ? (NTOK - row0) : RPW;

    const int yq  = lane / 7, xq  = lane - yq * 7;
    const int j2l = lane + 32;
    const int yq2 = j2l / 7,  xq2 = j2l - yq2 * 7;

    // ---- qk: all rows at once; kp2 read once per dim ----
    unsigned long long d12[RPW];
#pragma unroll
    for (int r = 0; r < RPW; r++) d12[r] = 0ull;

#pragma unroll
    for (int m = 0; m < 8; m++) {
        unsigned long long k0 = kp2[(4 * m + 0) * 32 + lane];
        unsigned long long k1 = kp2[(4 * m + 1) * 32 + lane];
        unsigned long long k2 = kp2[(4 * m + 2) * 32 + lane];
        unsigned long long k3 = kp2[(4 * m + 3) * 32 + lane];
#pragma unroll
        for (int r = 0; r < RPW; r++) {
            int i = row0 + ((r < nr) ? r : 0);         // clamp padding rows
            float4 qv = *(const float4*)&qs[i * HDIM + 4 * m];  // broadcast
            fma2(d12[r], k0, dup_f32(qv.x));
            fma2(d12[r], k1, dup_f32(qv.y));
            fma2(d12[r], k2, dup_f32(qv.z));
            fma2(d12[r], k3, dup_f32(qv.w));
        }
    }

    // ---- softmax per row (13 independent chains) ----
#pragma unroll
    for (int r = 0; r < RPW; r++) {
        int i = row0 + ((r < nr) ? r : 0);
        const int yi = i / 7, xi = i - yi * 7;
        const float* mrow = mrow_base + (size_t)i * NTOK;

        float d1, d2;
        unpack2(d12[r], d1, d2);
        float l1 = d1 * scale + bt[(yi - yq + 6) * 13 + (xi - xq + 6)] + mrow[lane];
        float p1 = __expf(l1);                      // logits bounded: no max-sub
        float p2 = 0.f;
        if (lane < NTOK - 32) {
            float l2 = d2 * scale + bt[(yi - yq2 + 6) * 13 + (xi - xq2 + 6)]
                     + mrow[j2l];
            p2 = __expf(l2);
        }
        float s = p1 + p2;
#pragma unroll
        for (int o = 16; o > 0; o >>= 1)
            s += __shfl_xor_sync(0xffffffffu, s, o);
        float inv = 1.f / s;
        pbuf[warp][r][lane]      = p1 * inv;
        pbuf[warp][r][lane + 32] = p2 * inv;        // zero for lane>=17
    }
    __syncwarp();

    // ---- p.v: all rows at once; vt read once per j-quad ----
    unsigned long long a2[RPW];
#pragma unroll
    for (int r = 0; r < RPW; r++) a2[r] = 0ull;

#pragma unroll
    for (int j4 = 0; j4 < 13; j4++) {
        ulonglong2 vq = *(const ulonglong2*)&vt[lane * VT_STRIDE + j4 * 4];
#pragma unroll
        for (int r = 0; r < RPW; r++) {
            ulonglong2 pq = *(const ulonglong2*)&pbuf[warp][r][j4 * 4]; // bcast
            fma2(a2[r], pq.x, vq.x);
            fma2(a2[r], pq.y, vq.y);
        }
    }

    // ---- store ----
#pragma unroll
    for (int r = 0; r < RPW; r++) {
        if (r < nr) {
            float alo_, ahi_;
            unpack2(a2[r], alo_, ahi_);
            float acc = alo_ + ahi_;
            int i = row0 + r;
            size_t oidx = ((size_t)b * NTOK + i) * DMODEL + h * HDIM + lane;
            __nv_bfloat16 hh = __float2bfloat16(acc);
            out_hi[oidx] = hh;
            out_lo[oidx] = __float2bfloat16(acc - __bfloat162float(hh));
        }
    }
}

// ---------------------------------------------------------------------------
// launch
// ---------------------------------------------------------------------------
extern "C" void kernel_launch(void* const* d_in, const int* in_sizes, int n_in,
                              void* d_out, int out_size)
{
    const float* x          = (const float*)d_in[0];
    const float* mask       = (const float*)d_in[1];
    const float* qkv_w      = (const float*)d_in[2];
    const float* qkv_b      = (const float*)d_in[3];
    const float* proj_w     = (const float*)d_in[4];
    const float* proj_b     = (const float*)d_in[5];
    const float* bias_table = (const float*)d_in[6];
    float* out = (float*)d_out;

    float *qkv_s;
    __nv_bfloat16 *xhi, *xlo, *ahi, *alo, *w1hi, *w1lo, *w2hi, *w2lo;
    cudaGetSymbolAddress((void**)&qkv_s, g_qkv);
    cudaGetSymbolAddress((void**)&xhi,  g_xhi);
    cudaGetSymbolAddress((void**)&xlo,  g_xlo);
    cudaGetSymbolAddress((void**)&ahi,  g_ahi);
    cudaGetSymbolAddress((void**)&alo,  g_alo);
    cudaGetSymbolAddress((void**)&w1hi, g_w1hi);
    cudaGetSymbolAddress((void**)&w1lo, g_w1lo);
    cudaGetSymbolAddress((void**)&w2hi, g_w2hi);
    cudaGetSymbolAddress((void**)&w2lo, g_w2lo);

    cudaFuncSetAttribute(gemm_mma_kernel,
                         cudaFuncAttributeMaxDynamicSharedMemorySize, SMEM_TOTAL);

    {
        int n4 = (MROWS * KDIM) / 4;
        split_kernel<<<(n4 + 255) / 256, 256>>>((const float4*)x,
                                                (uint2*)xhi, (uint2*)xlo, n4);
        dim3 g1(QKV_N / 32, KDIM / 32);
        wtrans_split_kernel<<<g1, 256>>>(qkv_w, w1hi, w1lo, KDIM, QKV_N);
        dim3 g2(DMODEL / 32, KDIM / 32);
        wtrans_split_kernel<<<g2, 256>>>(proj_w, w2hi, w2lo, KDIM, DMODEL);
    }
    {
        dim3 grid(QKV_N / BN, MROWS / BM);
        gemm_mma_kernel<<<grid, 256, SMEM_TOTAL>>>(xhi, xlo, w1hi, w1lo,
                                                   qkv_b, qkv_s, QKV_N);
    }
    attn_kernel<<<B_WIN * NHEADS, 128>>>(qkv_s, mask, bias_table, ahi, alo);
    {
        dim3 grid(DMODEL / BN, MROWS / BM);
        gemm_mma_kernel<<<grid, 256, SMEM_TOTAL>>>(ahi, alo, w2hi, w2lo,
                                                   proj_b, out, DMODEL);
    }
}

// round 9
// speedup vs baseline: 1.5336x; 1.3253x over previous
#include <cuda_runtime.h>
#include <cuda_fp16.h>
#include <cuda_bf16.h>
#include <cstdint>

// ---------------------------------------------------------------------------
// Problem constants
// ---------------------------------------------------------------------------
#define B_WIN   2048
#define NTOK    49
#define DMODEL  768
#define NHEADS  24
#define HDIM    32
#define NW      64
#define MROWS   (B_WIN * NTOK)     // 100352
#define QKV_N   (3 * DMODEL)       // 2304
#define KDIM    768
#define KPITCH  (KDIM * 2)         // bytes per K-major row (fp16)

// ---------------------------------------------------------------------------
// scratch (__device__ globals, allocation-free)
// ---------------------------------------------------------------------------
__device__ float  g_qkv [(size_t)MROWS * QKV_N];
__device__ __half g_x16 [(size_t)MROWS * KDIM];      // x as fp16
__device__ __half g_a16 [(size_t)MROWS * KDIM];      // attention out as fp16
__device__ __half g_w1hi[(size_t)QKV_N * KDIM];      // qkv_w^T hi [N,K]
__device__ __half g_w1lo[(size_t)QKV_N * KDIM];
__device__ __half g_w2hi[(size_t)DMODEL * KDIM];     // proj_w^T hi [N,K]
__device__ __half g_w2lo[(size_t)DMODEL * KDIM];

// ---------------------------------------------------------------------------
// PTX helpers
// ---------------------------------------------------------------------------
__device__ __forceinline__ void cp16(uint32_t dst, const void* src) {
    asm volatile("cp.async.cg.shared.global [%0], [%1], 16;"
                 :: "r"(dst), "l"((unsigned long long)__cvta_generic_to_global(src))
                 : "memory");
}
__device__ __forceinline__ void ldsm4(uint32_t* r, uint32_t addr) {
    asm volatile("ldmatrix.sync.aligned.m8n8.x4.shared.b16 {%0,%1,%2,%3}, [%4];"
                 : "=r"(r[0]), "=r"(r[1]), "=r"(r[2]), "=r"(r[3]) : "r"(addr));
}
__device__ __forceinline__ void mma_fp16(float* c, const uint32_t* a,
                                         uint32_t b0, uint32_t b1) {
    asm volatile(
        "mma.sync.aligned.m16n8k16.row.col.f32.f16.f16.f32 "
        "{%0,%1,%2,%3}, {%4,%5,%6,%7}, {%8,%9}, {%0,%1,%2,%3};"
        : "+f"(c[0]), "+f"(c[1]), "+f"(c[2]), "+f"(c[3])
        : "r"(a[0]), "r"(a[1]), "r"(a[2]), "r"(a[3]), "r"(b0), "r"(b1));
}
// packed fp32x2 (Blackwell FFMA2 — PTX-only)
__device__ __forceinline__ unsigned long long dup_f32(float x) {
    unsigned long long r;
    asm("mov.b64 %0, {%1, %1};" : "=l"(r) : "f"(x));
    return r;
}
__device__ __forceinline__ unsigned long long pack_f32(float lo, float hi) {
    unsigned long long r;
    asm("mov.b64 %0, {%1, %2};" : "=l"(r) : "f"(lo), "f"(hi));
    return r;
}
__device__ __forceinline__ void fma2(unsigned long long& d,
                                     unsigned long long a,
                                     unsigned long long b) {
    asm("fma.rn.f32x2 %0, %1, %2, %0;" : "+l"(d) : "l"(a), "l"(b));
}
__device__ __forceinline__ void unpack2(unsigned long long v, float& lo, float& hi) {
    asm("mov.b64 {%0, %1}, %2;" : "=f"(lo), "=f"(hi) : "l"(v));
}

// ---------------------------------------------------------------------------
// GEMM: C[M,N] = A_fp16[M,K] @ (Bhi+Blo)^T[N,K] + bias, fp32 out.
// 2-term fp16: A*Bhi + A*Blo. BM=128, BN=128, BK=32, 4-stage cp.async,
// 256 threads, 2 CTAs/SM. XOR-swizzled 64B smem rows.
// ---------------------------------------------------------------------------
#define BM 128
#define BN 128
#define BK 32
#define NCHUNK (KDIM / BK)      // 24
#define A_OFF   0
#define BHI_OFF 8192
#define BLO_OFF 16384
#define STG_B   24576
#define NSTAGE  4
#define SMEM_TOTAL (NSTAGE * STG_B)  // 98304

extern __shared__ char dyn_smem[];

__device__ __forceinline__ uint32_t swz_off(int row, int c16) {
    return (uint32_t)(row * 64 + (((c16) ^ ((row >> 1) & 3)) << 4));
}

__global__ void __launch_bounds__(256, 2)
gemm_mma_kernel(const __half* __restrict__ A,
                const __half* __restrict__ Bhi,
                const __half* __restrict__ Blo,
                const float* __restrict__ bias,
                float* __restrict__ C, int N)
{
    const uint32_t sb = (uint32_t)__cvta_generic_to_shared(dyn_smem);
    const int tid    = threadIdx.x;
    const int wid    = tid >> 5;
    const int lane   = tid & 31;
    const int warp_m = wid & 1;     // 64 rows
    const int warp_n = wid >> 1;    // 32 cols
    const int brow   = blockIdx.y * BM;
    const int bcol   = blockIdx.x * BN;

    const char* pA   = (const char*)A   + (size_t)brow * KPITCH;
    const char* pBhi = (const char*)Bhi + (size_t)bcol * KPITCH;
    const char* pBlo = (const char*)Blo + (size_t)bcol * KPITCH;

    float acc[4][4][4];
#pragma unroll
    for (int mt = 0; mt < 4; mt++)
#pragma unroll
        for (int nt = 0; nt < 4; nt++)
#pragma unroll
            for (int q = 0; q < 4; q++) acc[mt][nt][q] = 0.f;

    auto load_stage = [&](int c, int s) {
        const uint32_t st = sb + s * STG_B;
        const int koff = c * 64;
#pragma unroll
        for (int r = 0; r < 2; r++) {
            int p    = tid + r * 256;      // 0..511
            int row  = p >> 2;             // 0..127
            int c16  = p & 3;
            uint32_t so = swz_off(row, c16);
            size_t   go = (size_t)row * KPITCH + koff + c16 * 16;
            cp16(st + A_OFF   + so, pA + go);
            cp16(st + BHI_OFF + so, pBhi + go);
            cp16(st + BLO_OFF + so, pBlo + go);
        }
        asm volatile("cp.async.commit_group;" ::: "memory");
    };

    load_stage(0, 0);
    load_stage(1, 1);
    load_stage(2, 2);

    for (int c = 0; c < NCHUNK; c++) {
        if (c <= NCHUNK - 3)
            asm volatile("cp.async.wait_group 2;" ::: "memory");
        else if (c == NCHUNK - 2)
            asm volatile("cp.async.wait_group 1;" ::: "memory");
        else
            asm volatile("cp.async.wait_group 0;" ::: "memory");
        __syncthreads();

        if (c + 3 < NCHUNK) load_stage(c + 3, (c + 3) & 3);

        const uint32_t st = sb + (c & 3) * STG_B;
#pragma unroll
        for (int ks = 0; ks < 2; ks++) {
            uint32_t a[4][4];
#pragma unroll
            for (int mt = 0; mt < 4; mt++) {
                int row = warp_m * 64 + mt * 16 + (lane & 7) + ((lane >> 3) & 1) * 8;
                int c16 = 2 * ks + ((lane >> 4) & 1);
                ldsm4(a[mt], st + A_OFF + swz_off(row, c16));
            }
            uint32_t bh[2][4], bl[2][4];
#pragma unroll
            for (int np = 0; np < 2; np++) {
                int rowb = warp_n * 32 + np * 16 + (lane & 7) + ((lane >> 4) & 1) * 8;
                int c16  = 2 * ks + ((lane >> 3) & 1);
                uint32_t so = swz_off(rowb, c16);
                ldsm4(bh[np], st + BHI_OFF + so);
                ldsm4(bl[np], st + BLO_OFF + so);
            }
            // term-major: hi term then lo term (dep distance 16)
#pragma unroll
            for (int np = 0; np < 2; np++)
#pragma unroll
                for (int t = 0; t < 2; t++)
#pragma unroll
                    for (int mt = 0; mt < 4; mt++)
                        mma_fp16(acc[mt][np*2+t], a[mt], bh[np][t*2], bh[np][t*2+1]);
#pragma unroll
            for (int np = 0; np < 2; np++)
#pragma unroll
                for (int t = 0; t < 2; t++)
#pragma unroll
                    for (int mt = 0; mt < 4; mt++)
                        mma_fp16(acc[mt][np*2+t], a[mt], bl[np][t*2], bl[np][t*2+1]);
        }
    }

    const int row0 = brow + warp_m * 64;
    const int col0 = bcol + warp_n * 32;
#pragma unroll
    for (int mt = 0; mt < 4; mt++) {
#pragma unroll
        for (int nt = 0; nt < 4; nt++) {
            int r  = row0 + mt * 16 + (lane >> 2);
            int cc = col0 + nt * 8 + (lane & 3) * 2;
            float2 bv = *(const float2*)(bias + cc);
            float2 o0 = make_float2(acc[mt][nt][0] + bv.x, acc[mt][nt][1] + bv.y);
            float2 o1 = make_float2(acc[mt][nt][2] + bv.x, acc[mt][nt][3] + bv.y);
            *(float2*)(C + (size_t)r * N + cc)       = o0;
            *(float2*)(C + (size_t)(r + 8) * N + cc) = o1;
        }
    }
}

// ---------------------------------------------------------------------------
// convert f32 -> fp16 (single, RN)
// ---------------------------------------------------------------------------
__global__ void __launch_bounds__(256)
conv16_kernel(const float4* __restrict__ in, uint2* __restrict__ out, int n4)
{
    int i = blockIdx.x * 256 + threadIdx.x;
    if (i >= n4) return;
    float4 v = in[i];
    __half2 h0 = __floats2half2_rn(v.x, v.y);
    __half2 h1 = __floats2half2_rn(v.z, v.w);
    uint2 o;
    o.x = *(uint32_t*)&h0;
    o.y = *(uint32_t*)&h1;
    out[i] = o;
}

// ---------------------------------------------------------------------------
// weight transpose + fp16 split: W[K,N] f32 -> hi/lo[N,K] fp16
// ---------------------------------------------------------------------------
__global__ void __launch_bounds__(256)
wtrans_split_kernel(const float* __restrict__ W, __half* __restrict__ hi,
                    __half* __restrict__ lo, int K, int N)
{
    __shared__ float t[32][33];
    const int n0 = blockIdx.x * 32, k0 = blockIdx.y * 32;
    const int tx = threadIdx.x & 31, ty = threadIdx.x >> 5;
#pragma unroll
    for (int r = 0; r < 32; r += 8)
        t[ty + r][tx] = W[(size_t)(k0 + ty + r) * N + n0 + tx];
    __syncthreads();
#pragma unroll
    for (int r = 0; r < 32; r += 8) {
        float v = t[tx][ty + r];
        size_t o = (size_t)(n0 + ty + r) * K + k0 + tx;
        __half h = __float2half_rn(v);
        hi[o] = h;
        lo[o] = __float2half_rn(v - __half2float(h));
    }
}

// ---------------------------------------------------------------------------
// Attention: one CTA per (window, head), 128 threads / 4 warps, ROW-BATCHED
// (13 rows per warp simultaneously). Output: single fp16.
// ---------------------------------------------------------------------------
#define VT_STRIDE 52
#define RPW 13

__global__ void __launch_bounds__(128)
attn_kernel(const float* __restrict__ qkv,
            const float* __restrict__ mask,
            const float* __restrict__ bias_table,
            __half* __restrict__ out16)
{
    const int bh = blockIdx.x;
    const int b  = bh / NHEADS;
    const int h  = bh - b * NHEADS;
    const int w  = b & (NW - 1);

    __shared__ float qs[NTOK * HDIM];
    __shared__ unsigned long long kp2[HDIM * 32];
    __shared__ float vt[HDIM * VT_STRIDE];
    __shared__ float pbuf[4][RPW][64];
    __shared__ float bt[169];

    const int tid  = threadIdx.x;
    const int warp = tid >> 5, lane = tid & 31;
    const float* base = qkv + (size_t)b * NTOK * QKV_N + h * HDIM;

    for (int idx = tid; idx < NTOK * 8; idx += 128) {
        int i = idx >> 3, m = idx & 7;
        *(float4*)&qs[i * HDIM + m * 4] =
            *(const float4*)(base + (size_t)i * QKV_N + m * 4);
    }
    {
        const int d0 = warp * 8;
        const int j  = lane;
        float4 a1 = *(const float4*)(base + (size_t)j * QKV_N + DMODEL + d0);
        float4 b1 = *(const float4*)(base + (size_t)j * QKV_N + DMODEL + d0 + 4);
        float4 a2 = make_float4(0.f, 0.f, 0.f, 0.f);
        float4 b2 = make_float4(0.f, 0.f, 0.f, 0.f);
        if (j < NTOK - 32) {
            a2 = *(const float4*)(base + (size_t)(j + 32) * QKV_N + DMODEL + d0);
            b2 = *(const float4*)(base + (size_t)(j + 32) * QKV_N + DMODEL + d0 + 4);
        }
        kp2[(d0 + 0) * 32 + j] = pack_f32(a1.x, a2.x);
        kp2[(d0 + 1) * 32 + j] = pack_f32(a1.y, a2.y);
        kp2[(d0 + 2) * 32 + j] = pack_f32(a1.z, a2.z);
        kp2[(d0 + 3) * 32 + j] = pack_f32(a1.w, a2.w);
        kp2[(d0 + 4) * 32 + j] = pack_f32(b1.x, b2.x);
        kp2[(d0 + 5) * 32 + j] = pack_f32(b1.y, b2.y);
        kp2[(d0 + 6) * 32 + j] = pack_f32(b1.z, b2.z);
        kp2[(d0 + 7) * 32 + j] = pack_f32(b1.w, b2.w);
    }
    if (tid < NTOK) {
        const float* vrow = base + (size_t)tid * QKV_N + 2 * DMODEL;
#pragma unroll
        for (int m = 0; m < 8; m++) {
            float4 vv = *(const float4*)(vrow + 4 * m);
            vt[(4 * m + 0) * VT_STRIDE + tid] = vv.x;
            vt[(4 * m + 1) * VT_STRIDE + tid] = vv.y;
            vt[(4 * m + 2) * VT_STRIDE + tid] = vv.z;
            vt[(4 * m + 3) * VT_STRIDE + tid] = vv.w;
        }
    }
    if (tid >= 64 && tid < 96) {
        int d = tid - 64;
        vt[d * VT_STRIDE + 49] = 0.f;
        vt[d * VT_STRIDE + 50] = 0.f;
        vt[d * VT_STRIDE + 51] = 0.f;
    }
    for (int idx = tid; idx < 169; idx += 128)
        bt[idx] = bias_table[idx * NHEADS + h];
    __syncthreads();

    const float scale = 0.17677669529663687f;
    const float* mrow_base = mask + (size_t)w * NTOK * NTOK;

    const int row0 = warp * RPW;
    const int nr   = (NTOK - row0 < RPW) ? (NTOK - row0) : RPW;

    const int yq  = lane / 7, xq  = lane - yq * 7;
    const int j2l = lane + 32;
    const int yq2 = j2l / 7,  xq2 = j2l - yq2 * 7;

    unsigned long long d12[RPW];
#pragma unroll
    for (int r = 0; r < RPW; r++) d12[r] = 0ull;

#pragma unroll
    for (int m = 0; m < 8; m++) {
        unsigned long long k0 = kp2[(4 * m + 0) * 32 + lane];
        unsigned long long k1 = kp2[(4 * m + 1) * 32 + lane];
        unsigned long long k2 = kp2[(4 * m + 2) * 32 + lane];
        unsigned long long k3 = kp2[(4 * m + 3) * 32 + lane];
#pragma unroll
        for (int r = 0; r < RPW; r++) {
            int i = row0 + ((r < nr) ? r : 0);
            float4 qv = *(const float4*)&qs[i * HDIM + 4 * m];
            fma2(d12[r], k0, dup_f32(qv.x));
            fma2(d12[r], k1, dup_f32(qv.y));
            fma2(d12[r], k2, dup_f32(qv.z));
            fma2(d12[r], k3, dup_f32(qv.w));
        }
    }

#pragma unroll
    for (int r = 0; r < RPW; r++) {
        int i = row0 + ((r < nr) ? r : 0);
        const int yi = i / 7, xi = i - yi * 7;
        const float* mrow = mrow_base + (size_t)i * NTOK;

        float d1, d2;
        unpack2(d12[r], d1, d2);
        float l1 = d1 * scale + bt[(yi - yq + 6) * 13 + (xi - xq + 6)] + mrow[lane];
        float p1 = __expf(l1);
        float p2 = 0.f;
        if (lane < NTOK - 32) {
            float l2 = d2 * scale + bt[(yi - yq2 + 6) * 13 + (xi - xq2 + 6)]
                     + mrow[j2l];
            p2 = __expf(l2);
        }
        float s = p1 + p2;
#pragma unroll
        for (int o = 16; o > 0; o >>= 1)
            s += __shfl_xor_sync(0xffffffffu, s, o);
        float inv = 1.f / s;
        pbuf[warp][r][lane]      = p1 * inv;
        pbuf[warp][r][lane + 32] = p2 * inv;
    }
    __syncwarp();

    unsigned long long a2[RPW];
#pragma unroll
    for (int r = 0; r < RPW; r++) a2[r] = 0ull;

#pragma unroll
    for (int j4 = 0; j4 < 13; j4++) {
        ulonglong2 vq = *(const ulonglong2*)&vt[lane * VT_STRIDE + j4 * 4];
#pragma unroll
        for (int r = 0; r < RPW; r++) {
            ulonglong2 pq = *(const ulonglong2*)&pbuf[warp][r][j4 * 4];
            fma2(a2[r], pq.x, vq.x);
            fma2(a2[r], pq.y, vq.y);
        }
    }

#pragma unroll
    for (int r = 0; r < RPW; r++) {
        if (r < nr) {
            float alo_, ahi_;
            unpack2(a2[r], alo_, ahi_);
            float acc = alo_ + ahi_;
            int i = row0 + r;
            size_t oidx = ((size_t)b * NTOK + i) * DMODEL + h * HDIM + lane;
            out16[oidx] = __float2half_rn(acc);
        }
    }
}

// ---------------------------------------------------------------------------
// launch
// ---------------------------------------------------------------------------
extern "C" void kernel_launch(void* const* d_in, const int* in_sizes, int n_in,
                              void* d_out, int out_size)
{
    const float* x          = (const float*)d_in[0];
    const float* mask       = (const float*)d_in[1];
    const float* qkv_w      = (const float*)d_in[2];
    const float* qkv_b      = (const float*)d_in[3];
    const float* proj_w     = (const float*)d_in[4];
    const float* proj_b     = (const float*)d_in[5];
    const float* bias_table = (const float*)d_in[6];
    float* out = (float*)d_out;

    float *qkv_s;
    __half *x16, *a16, *w1hi, *w1lo, *w2hi, *w2lo;
    cudaGetSymbolAddress((void**)&qkv_s, g_qkv);
    cudaGetSymbolAddress((void**)&x16,  g_x16);
    cudaGetSymbolAddress((void**)&a16,  g_a16);
    cudaGetSymbolAddress((void**)&w1hi, g_w1hi);
    cudaGetSymbolAddress((void**)&w1lo, g_w1lo);
    cudaGetSymbolAddress((void**)&w2hi, g_w2hi);
    cudaGetSymbolAddress((void**)&w2lo, g_w2lo);

    cudaFuncSetAttribute(gemm_mma_kernel,
                         cudaFuncAttributeMaxDynamicSharedMemorySize, SMEM_TOTAL);

    // 0) conversions
    {
        int n4 = (MROWS * KDIM) / 4;
        conv16_kernel<<<(n4 + 255) / 256, 256>>>((const float4*)x, (uint2*)x16, n4);
        dim3 g1(QKV_N / 32, KDIM / 32);
        wtrans_split_kernel<<<g1, 256>>>(qkv_w, w1hi, w1lo, KDIM, QKV_N);
        dim3 g2(DMODEL / 32, KDIM / 32);
        wtrans_split_kernel<<<g2, 256>>>(proj_w, w2hi, w2lo, KDIM, DMODEL);
    }
    // 1) QKV GEMM (2-term fp16)
    {
        dim3 grid(QKV_N / BN, MROWS / BM);
        gemm_mma_kernel<<<grid, 256, SMEM_TOTAL>>>(x16, w1hi, w1lo,
                                                   qkv_b, qkv_s, QKV_N);
    }
    // 2) attention (row-batched), fp16 out
    attn_kernel<<<B_WIN * NHEADS, 128>>>(qkv_s, mask, bias_table, a16);

    // 3) proj GEMM (2-term fp16) -> d_out
    {
        dim3 grid(DMODEL / BN, MROWS / BM);
        gemm_mma_kernel<<<grid, 256, SMEM_TOTAL>>>(a16, w2hi, w2lo,
                                                   proj_b, out, DMODEL);
    }
}